// round 1
// baseline (speedup 1.0000x reference)
#include <cuda_runtime.h>
#include <cstdint>
#include <cstddef>

// Problem constants
// B=8, N=1024, C=1024, H=16, D=64, scale = D^-0.5 = 0.125
#define BB 8
#define NN 1024
#define CC 1024
#define HH 16
#define DD 64
#define SCALE 0.125f

// Scratch (device globals: allocation at module load, permitted by harness rules)
__device__ float g_qkv[(size_t)BB * NN * 3 * CC];   // (B,N,3,H,D) = (8192, 3072)
__device__ float g_ctx[(size_t)BB * NN * CC];       // (B,N,H*D)   = (8192, 1024)

// ---------------------------------------------------------------------------
// Generic tiled SGEMM with bias: C[M,N] = A[M,K] @ B[K,N] + bias[N]
// 128x128 block tile, BK=8, 256 threads, 8x8 per thread.
// Requires M%128==0, N%128==0, K%8==0.
// ---------------------------------------------------------------------------
__global__ __launch_bounds__(256) void sgemm_bias(
    const float* __restrict__ A, const float* __restrict__ Bm,
    const float* __restrict__ bias, float* __restrict__ C,
    int M, int N, int K)
{
    __shared__ float As[8][128];
    __shared__ float Bs[8][128];

    const int tid  = threadIdx.x;
    const int brow = blockIdx.y * 128;
    const int bcol = blockIdx.x * 128;

    const int arow = tid >> 1;          // 0..127
    const int acol = (tid & 1) * 4;     // 0 or 4
    const int bkr  = tid >> 5;          // 0..7
    const int bkc  = (tid & 31) * 4;    // 0..124

    const int ty = tid >> 4;            // 0..15
    const int tx = tid & 15;            // 0..15

    float acc[8][8];
#pragma unroll
    for (int i = 0; i < 8; i++)
#pragma unroll
        for (int j = 0; j < 8; j++) acc[i][j] = 0.0f;

    for (int k0 = 0; k0 < K; k0 += 8) {
        float4 av = *reinterpret_cast<const float4*>(
            &A[(size_t)(brow + arow) * K + k0 + acol]);
        As[acol + 0][arow] = av.x;
        As[acol + 1][arow] = av.y;
        As[acol + 2][arow] = av.z;
        As[acol + 3][arow] = av.w;

        float4 bv = *reinterpret_cast<const float4*>(
            &Bm[(size_t)(k0 + bkr) * N + bcol + bkc]);
        *reinterpret_cast<float4*>(&Bs[bkr][bkc]) = bv;

        __syncthreads();

#pragma unroll
        for (int kk = 0; kk < 8; kk++) {
            float ar[8], br[8];
            float4 a0 = *reinterpret_cast<const float4*>(&As[kk][ty * 8]);
            float4 a1 = *reinterpret_cast<const float4*>(&As[kk][ty * 8 + 4]);
            float4 b0 = *reinterpret_cast<const float4*>(&Bs[kk][tx * 8]);
            float4 b1 = *reinterpret_cast<const float4*>(&Bs[kk][tx * 8 + 4]);
            ar[0]=a0.x; ar[1]=a0.y; ar[2]=a0.z; ar[3]=a0.w;
            ar[4]=a1.x; ar[5]=a1.y; ar[6]=a1.z; ar[7]=a1.w;
            br[0]=b0.x; br[1]=b0.y; br[2]=b0.z; br[3]=b0.w;
            br[4]=b1.x; br[5]=b1.y; br[6]=b1.z; br[7]=b1.w;
#pragma unroll
            for (int i = 0; i < 8; i++)
#pragma unroll
                for (int j = 0; j < 8; j++)
                    acc[i][j] += ar[i] * br[j];
        }
        __syncthreads();
    }

#pragma unroll
    for (int i = 0; i < 8; i++) {
        const int row = brow + ty * 8 + i;
#pragma unroll
        for (int j = 0; j < 8; j += 4) {
            const int col = bcol + tx * 8 + j;
            float4 o;
            o.x = acc[i][j + 0] + bias[col + 0];
            o.y = acc[i][j + 1] + bias[col + 1];
            o.z = acc[i][j + 2] + bias[col + 2];
            o.w = acc[i][j + 3] + bias[col + 3];
            *reinterpret_cast<float4*>(&C[(size_t)row * N + col]) = o;
        }
    }
}

// ---------------------------------------------------------------------------
// Scores: attn_raw[bh, n, m] = SCALE * sum_d q[bh,n,d] * k[bh,m,d]
// q,k live inside g_qkv (B,N,3,H,D). Block: 64x64 output tile, 256 threads.
// ---------------------------------------------------------------------------
__global__ __launch_bounds__(256) void qk_scores(
    const float* __restrict__ qkv, float* __restrict__ attn)
{
    const int bh = blockIdx.z;           // 0..127
    const int b  = bh >> 4;
    const int h  = bh & 15;
    const int n0 = blockIdx.y * 64;
    const int m0 = blockIdx.x * 64;

    __shared__ float Qs[64][68];   // [d][row], padded
    __shared__ float Ks[64][68];   // [d][col]

    const float* qbase = qkv + (size_t)b * NN * 3 * CC + h * DD;          // s=0
    const float* kbase = qbase + CC;                                       // s=1

    const int tid = threadIdx.x;
    for (int i = tid; i < 64 * 16; i += 256) {
        const int r = i >> 4;
        const int c = (i & 15) * 4;
        float4 qv = *reinterpret_cast<const float4*>(
            qbase + (size_t)(n0 + r) * (3 * CC) + c);
        Qs[c + 0][r] = qv.x; Qs[c + 1][r] = qv.y;
        Qs[c + 2][r] = qv.z; Qs[c + 3][r] = qv.w;
        float4 kv = *reinterpret_cast<const float4*>(
            kbase + (size_t)(m0 + r) * (3 * CC) + c);
        Ks[c + 0][r] = kv.x; Ks[c + 1][r] = kv.y;
        Ks[c + 2][r] = kv.z; Ks[c + 3][r] = kv.w;
    }
    __syncthreads();

    const int ty = tid >> 4;
    const int tx = tid & 15;
    float acc[4][4];
#pragma unroll
    for (int i = 0; i < 4; i++)
#pragma unroll
        for (int j = 0; j < 4; j++) acc[i][j] = 0.0f;

#pragma unroll 8
    for (int d = 0; d < 64; d++) {
        float4 q4 = *reinterpret_cast<const float4*>(&Qs[d][ty * 4]);
        float4 k4 = *reinterpret_cast<const float4*>(&Ks[d][tx * 4]);
        float qa[4] = {q4.x, q4.y, q4.z, q4.w};
        float ka[4] = {k4.x, k4.y, k4.z, k4.w};
#pragma unroll
        for (int i = 0; i < 4; i++)
#pragma unroll
            for (int j = 0; j < 4; j++)
                acc[i][j] += qa[i] * ka[j];
    }

#pragma unroll
    for (int i = 0; i < 4; i++) {
        float4 o;
        o.x = acc[i][0] * SCALE;
        o.y = acc[i][1] * SCALE;
        o.z = acc[i][2] * SCALE;
        o.w = acc[i][3] * SCALE;
        *reinterpret_cast<float4*>(
            attn + ((size_t)bh * NN + n0 + ty * 4 + i) * NN + m0 + tx * 4) = o;
    }
}

// ---------------------------------------------------------------------------
// Row softmax in place over attn (B*H*N rows of length 1024).
// One 256-thread block per row, 4 elements/thread.
// ---------------------------------------------------------------------------
__global__ __launch_bounds__(256) void softmax_rows(float* __restrict__ attn)
{
    const size_t row = blockIdx.x;
    float* p = attn + row * NN;
    const int tid = threadIdx.x;

    float4 v = reinterpret_cast<float4*>(p)[tid];
    float m = fmaxf(fmaxf(v.x, v.y), fmaxf(v.z, v.w));

    __shared__ float red[8];
#pragma unroll
    for (int o = 16; o; o >>= 1)
        m = fmaxf(m, __shfl_xor_sync(0xffffffffu, m, o));
    if ((tid & 31) == 0) red[tid >> 5] = m;
    __syncthreads();
    m = red[0];
#pragma unroll
    for (int w = 1; w < 8; w++) m = fmaxf(m, red[w]);

    v.x = __expf(v.x - m);
    v.y = __expf(v.y - m);
    v.z = __expf(v.z - m);
    v.w = __expf(v.w - m);
    float s = v.x + v.y + v.z + v.w;
#pragma unroll
    for (int o = 16; o; o >>= 1)
        s += __shfl_xor_sync(0xffffffffu, s, o);
    __syncthreads();               // red reuse
    if ((tid & 31) == 0) red[tid >> 5] = s;
    __syncthreads();
    s = red[0];
#pragma unroll
    for (int w = 1; w < 8; w++) s += red[w];

    const float inv = 1.0f / s;
    v.x *= inv; v.y *= inv; v.z *= inv; v.w *= inv;
    reinterpret_cast<float4*>(p)[tid] = v;
}

// ---------------------------------------------------------------------------
// Context: ctx[b, n, h*64+d] = sum_m attn[bh,n,m] * v[bh,m,d]
// Block: 64 query rows x 64 d-cols (full D), K-tiles of 64 over m.
// ---------------------------------------------------------------------------
__global__ __launch_bounds__(256) void av_ctx(
    const float* __restrict__ attn, const float* __restrict__ qkv,
    float* __restrict__ ctx)
{
    const int bh = blockIdx.y;
    const int b  = bh >> 4;
    const int h  = bh & 15;
    const int n0 = blockIdx.x * 64;

    __shared__ float At[64][68];   // [m][row] transposed
    __shared__ float Vs[64][68];   // [m][d]

    const float* vbase = qkv + (size_t)b * NN * 3 * CC + 2 * CC + h * DD;  // s=2
    const float* arow  = attn + ((size_t)bh * NN + n0) * NN;

    const int tid = threadIdx.x;
    const int ty = tid >> 4;
    const int tx = tid & 15;

    float acc[4][4];
#pragma unroll
    for (int i = 0; i < 4; i++)
#pragma unroll
        for (int j = 0; j < 4; j++) acc[i][j] = 0.0f;

    for (int k0 = 0; k0 < NN; k0 += 64) {
        for (int i = tid; i < 64 * 16; i += 256) {
            const int r = i >> 4;
            const int c = (i & 15) * 4;
            float4 av = *reinterpret_cast<const float4*>(
                arow + (size_t)r * NN + k0 + c);
            At[c + 0][r] = av.x; At[c + 1][r] = av.y;
            At[c + 2][r] = av.z; At[c + 3][r] = av.w;
            float4 vv = *reinterpret_cast<const float4*>(
                vbase + (size_t)(k0 + r) * (3 * CC) + c);
            *reinterpret_cast<float4*>(&Vs[r][c]) = vv;
        }
        __syncthreads();

#pragma unroll 8
        for (int kk = 0; kk < 64; kk++) {
            float4 a4 = *reinterpret_cast<const float4*>(&At[kk][ty * 4]);
            float4 v4 = *reinterpret_cast<const float4*>(&Vs[kk][tx * 4]);
            float aa[4] = {a4.x, a4.y, a4.z, a4.w};
            float vv[4] = {v4.x, v4.y, v4.z, v4.w};
#pragma unroll
            for (int i = 0; i < 4; i++)
#pragma unroll
                for (int j = 0; j < 4; j++)
                    acc[i][j] += aa[i] * vv[j];
        }
        __syncthreads();
    }

#pragma unroll
    for (int i = 0; i < 4; i++) {
        float4 o = {acc[i][0], acc[i][1], acc[i][2], acc[i][3]};
        *reinterpret_cast<float4*>(
            ctx + ((size_t)b * NN + n0 + ty * 4 + i) * CC + h * DD + tx * 4) = o;
    }
}

// ---------------------------------------------------------------------------
extern "C" void kernel_launch(void* const* d_in, const int* in_sizes, int n_in,
                              void* d_out, int out_size)
{
    (void)in_sizes; (void)n_in; (void)out_size;
    const float* x      = (const float*)d_in[0];   // (8,1024,1024)
    const float* w_qkv  = (const float*)d_in[1];   // (1024,3072)
    const float* b_qkv  = (const float*)d_in[2];   // (3072,)
    const float* w_proj = (const float*)d_in[3];   // (1024,1024)
    const float* b_proj = (const float*)d_in[4];   // (1024,)

    float* out  = (float*)d_out;                        // (8,1024,1024)
    float* attn = out + (size_t)BB * NN * CC;           // (8,16,1024,1024)

    float* qkvp = nullptr;
    float* ctxp = nullptr;
    cudaGetSymbolAddress((void**)&qkvp, g_qkv);
    cudaGetSymbolAddress((void**)&ctxp, g_ctx);

    // 1) QKV projection: (8192,1024)@(1024,3072)+bias -> g_qkv
    sgemm_bias<<<dim3(3 * CC / 128, BB * NN / 128), 256>>>(
        x, w_qkv, b_qkv, qkvp, BB * NN, 3 * CC, CC);

    // 2) Raw scores -> attn region of d_out
    qk_scores<<<dim3(NN / 64, NN / 64, BB * HH), 256>>>(qkvp, attn);

    // 3) Softmax in place (final attn output)
    softmax_rows<<<(unsigned)(BB * HH * NN), 256>>>(attn);

    // 4) attn @ v -> ctx in (B,N,H,D) layout
    av_ctx<<<dim3(NN / 64, BB * HH), 256>>>(attn, qkvp, ctxp);

    // 5) Output projection: (8192,1024)@(1024,1024)+bias -> out
    sgemm_bias<<<dim3(CC / 128, BB * NN / 128), 256>>>(
        ctxp, w_proj, b_proj, out, BB * NN, CC, CC);
}

// round 2
// speedup vs baseline: 2.0825x; 2.0825x over previous
#include <cuda_runtime.h>
#include <cstdint>
#include <cstddef>

// B=8, N=1024, C=1024, H=16, D=64, scale = 0.125
#define BB 8
#define NN 1024
#define CC 1024
#define HH 16
#define DD 64
#define SCALE 0.125f

__device__ float g_qkv[(size_t)BB * NN * 3 * CC];   // (B,N,3,H,D)
__device__ float g_ctx[(size_t)BB * NN * CC];       // (B,N,H*D)

__device__ __forceinline__ unsigned f2tf(float f) {
    unsigned u;
    asm("cvt.rna.tf32.f32 %0, %1;" : "=r"(u) : "f"(f));
    return u;
}

__device__ __forceinline__ void mma_tf32(float c[4],
    unsigned a0, unsigned a1, unsigned a2, unsigned a3,
    unsigned b0, unsigned b1)
{
    asm volatile(
        "mma.sync.aligned.m16n8k8.row.col.f32.tf32.tf32.f32 "
        "{%0,%1,%2,%3}, {%4,%5,%6,%7}, {%8,%9}, {%0,%1,%2,%3};\n"
        : "+f"(c[0]), "+f"(c[1]), "+f"(c[2]), "+f"(c[3])
        : "r"(a0), "r"(a1), "r"(a2), "r"(a3), "r"(b0), "r"(b1));
}

// ---------------------------------------------------------------------------
// TF32 tensor-core SGEMM + bias: C[M,N] = A[M,K] @ B[K,N] + bias[N]
// 128x128 block tile, BK=16, 256 threads (8 warps, 4x2), warp tile 32x64.
// ---------------------------------------------------------------------------
__global__ __launch_bounds__(256) void sgemm_bias_tc(
    const float* __restrict__ A, const float* __restrict__ Bm,
    const float* __restrict__ bias, float* __restrict__ C,
    int M, int N, int K)
{
    __shared__ unsigned As[16][136];   // [k][m]
    __shared__ unsigned Bs[16][136];   // [k][n]

    const int tid  = threadIdx.x;
    const int brow = blockIdx.y * 128;
    const int bcol = blockIdx.x * 128;
    const int w  = tid >> 5, l = tid & 31;
    const int wr = w >> 1, wc = w & 1;
    const int g  = l >> 2, t = l & 3;

    const int ar  = tid >> 1;        // A fill row 0..127
    const int ac4 = (tid & 1) * 2;   // A fill float4-col base (0 or 2)

    float acc[2][8][4];
#pragma unroll
    for (int i = 0; i < 2; i++)
#pragma unroll
        for (int j = 0; j < 8; j++)
#pragma unroll
            for (int r = 0; r < 4; r++) acc[i][j][r] = 0.0f;

    for (int k0 = 0; k0 < K; k0 += 16) {
#pragma unroll
        for (int j = 0; j < 2; j++) {
            const int c4 = ac4 + j;
            float4 v = *reinterpret_cast<const float4*>(
                &A[(size_t)(brow + ar) * K + k0 + c4 * 4]);
            As[c4 * 4 + 0][ar] = f2tf(v.x);
            As[c4 * 4 + 1][ar] = f2tf(v.y);
            As[c4 * 4 + 2][ar] = f2tf(v.z);
            As[c4 * 4 + 3][ar] = f2tf(v.w);
        }
#pragma unroll
        for (int j = 0; j < 2; j++) {
            const int idx = tid * 2 + j;
            const int r = idx >> 5, c4 = idx & 31;
            float4 v = *reinterpret_cast<const float4*>(
                &Bm[(size_t)(k0 + r) * N + bcol + c4 * 4]);
            uint4 u = {f2tf(v.x), f2tf(v.y), f2tf(v.z), f2tf(v.w)};
            *reinterpret_cast<uint4*>(&Bs[r][c4 * 4]) = u;
        }
        __syncthreads();

#pragma unroll
        for (int kk = 0; kk < 16; kk += 8) {
            unsigned a[2][4], b[8][2];
#pragma unroll
            for (int i = 0; i < 2; i++) {
                const int m0 = wr * 32 + i * 16;
                a[i][0] = As[kk + t][m0 + g];
                a[i][1] = As[kk + t][m0 + g + 8];
                a[i][2] = As[kk + t + 4][m0 + g];
                a[i][3] = As[kk + t + 4][m0 + g + 8];
            }
#pragma unroll
            for (int j = 0; j < 8; j++) {
                const int n0 = wc * 64 + j * 8;
                b[j][0] = Bs[kk + t][n0 + g];
                b[j][1] = Bs[kk + t + 4][n0 + g];
            }
#pragma unroll
            for (int i = 0; i < 2; i++)
#pragma unroll
                for (int j = 0; j < 8; j++)
                    mma_tf32(acc[i][j], a[i][0], a[i][1], a[i][2], a[i][3],
                             b[j][0], b[j][1]);
        }
        __syncthreads();
    }

#pragma unroll
    for (int j = 0; j < 8; j++) {
        const int col = bcol + wc * 64 + j * 8 + t * 2;
        const float b0 = bias[col], b1 = bias[col + 1];
#pragma unroll
        for (int i = 0; i < 2; i++) {
            const int r0 = brow + wr * 32 + i * 16;
            float2 o0 = {acc[i][j][0] + b0, acc[i][j][1] + b1};
            float2 o1 = {acc[i][j][2] + b0, acc[i][j][3] + b1};
            *reinterpret_cast<float2*>(&C[(size_t)(r0 + g) * N + col]) = o0;
            *reinterpret_cast<float2*>(&C[(size_t)(r0 + g + 8) * N + col]) = o1;
        }
    }
}

// ---------------------------------------------------------------------------
// QK^T scores (tf32 tensor): attn_raw[bh,n,m] = (SCALE*q[n,:]) . k[m,:]
// 128x128 tile, inner K = 64 (BK=16 x 4 iters).
// ---------------------------------------------------------------------------
__global__ __launch_bounds__(256) void qk_scores_tc(
    const float* __restrict__ qkv, float* __restrict__ attn)
{
    __shared__ unsigned As[16][136];   // [d][n]  (Q, pre-scaled)
    __shared__ unsigned Bs[16][136];   // [d][m]  (K)

    const int bh = blockIdx.z;
    const int b  = bh >> 4;
    const int h  = bh & 15;
    const int n0 = blockIdx.y * 128;
    const int m0 = blockIdx.x * 128;

    const float* qbase = qkv + (size_t)b * NN * 3 * CC + h * DD;       // s=0
    const float* kbase = qbase + CC;                                    // s=1

    const int tid = threadIdx.x;
    const int w  = tid >> 5, l = tid & 31;
    const int wr = w >> 1, wc = w & 1;
    const int g  = l >> 2, t = l & 3;
    const int ar  = tid >> 1;
    const int ac4 = (tid & 1) * 2;

    float acc[2][8][4];
#pragma unroll
    for (int i = 0; i < 2; i++)
#pragma unroll
        for (int j = 0; j < 8; j++)
#pragma unroll
            for (int r = 0; r < 4; r++) acc[i][j][r] = 0.0f;

    for (int k0 = 0; k0 < DD; k0 += 16) {
#pragma unroll
        for (int j = 0; j < 2; j++) {
            const int c4 = ac4 + j;
            float4 qv = *reinterpret_cast<const float4*>(
                qbase + (size_t)(n0 + ar) * (3 * CC) + k0 + c4 * 4);
            As[c4 * 4 + 0][ar] = f2tf(qv.x * SCALE);
            As[c4 * 4 + 1][ar] = f2tf(qv.y * SCALE);
            As[c4 * 4 + 2][ar] = f2tf(qv.z * SCALE);
            As[c4 * 4 + 3][ar] = f2tf(qv.w * SCALE);
            float4 kv = *reinterpret_cast<const float4*>(
                kbase + (size_t)(m0 + ar) * (3 * CC) + k0 + c4 * 4);
            Bs[c4 * 4 + 0][ar] = f2tf(kv.x);
            Bs[c4 * 4 + 1][ar] = f2tf(kv.y);
            Bs[c4 * 4 + 2][ar] = f2tf(kv.z);
            Bs[c4 * 4 + 3][ar] = f2tf(kv.w);
        }
        __syncthreads();

#pragma unroll
        for (int kk = 0; kk < 16; kk += 8) {
            unsigned a[2][4], bfr[8][2];
#pragma unroll
            for (int i = 0; i < 2; i++) {
                const int mm = wr * 32 + i * 16;
                a[i][0] = As[kk + t][mm + g];
                a[i][1] = As[kk + t][mm + g + 8];
                a[i][2] = As[kk + t + 4][mm + g];
                a[i][3] = As[kk + t + 4][mm + g + 8];
            }
#pragma unroll
            for (int j = 0; j < 8; j++) {
                const int nn = wc * 64 + j * 8;
                bfr[j][0] = Bs[kk + t][nn + g];
                bfr[j][1] = Bs[kk + t + 4][nn + g];
            }
#pragma unroll
            for (int i = 0; i < 2; i++)
#pragma unroll
                for (int j = 0; j < 8; j++)
                    mma_tf32(acc[i][j], a[i][0], a[i][1], a[i][2], a[i][3],
                             bfr[j][0], bfr[j][1]);
        }
        __syncthreads();
    }

    float* arow = attn + (size_t)bh * NN * NN;
#pragma unroll
    for (int j = 0; j < 8; j++) {
        const int col = m0 + wc * 64 + j * 8 + t * 2;
#pragma unroll
        for (int i = 0; i < 2; i++) {
            const int r0 = n0 + wr * 32 + i * 16;
            float2 o0 = {acc[i][j][0], acc[i][j][1]};
            float2 o1 = {acc[i][j][2], acc[i][j][3]};
            *reinterpret_cast<float2*>(&arow[(size_t)(r0 + g) * NN + col]) = o0;
            *reinterpret_cast<float2*>(&arow[(size_t)(r0 + g + 8) * NN + col]) = o1;
        }
    }
}

// ---------------------------------------------------------------------------
// Row softmax in place (B*H*N rows of 1024). 256 threads/row.
// ---------------------------------------------------------------------------
__global__ __launch_bounds__(256) void softmax_rows(float* __restrict__ attn)
{
    const size_t row = blockIdx.x;
    float* p = attn + row * NN;
    const int tid = threadIdx.x;

    float4 v = reinterpret_cast<float4*>(p)[tid];
    float m = fmaxf(fmaxf(v.x, v.y), fmaxf(v.z, v.w));

    __shared__ float red[8];
#pragma unroll
    for (int o = 16; o; o >>= 1)
        m = fmaxf(m, __shfl_xor_sync(0xffffffffu, m, o));
    if ((tid & 31) == 0) red[tid >> 5] = m;
    __syncthreads();
    m = red[0];
#pragma unroll
    for (int wv = 1; wv < 8; wv++) m = fmaxf(m, red[wv]);

    v.x = __expf(v.x - m);
    v.y = __expf(v.y - m);
    v.z = __expf(v.z - m);
    v.w = __expf(v.w - m);
    float s = v.x + v.y + v.z + v.w;
#pragma unroll
    for (int o = 16; o; o >>= 1)
        s += __shfl_xor_sync(0xffffffffu, s, o);
    __syncthreads();
    if ((tid & 31) == 0) red[tid >> 5] = s;
    __syncthreads();
    s = red[0];
#pragma unroll
    for (int wv = 1; wv < 8; wv++) s += red[wv];

    const float inv = 1.0f / s;
    v.x *= inv; v.y *= inv; v.z *= inv; v.w *= inv;
    reinterpret_cast<float4*>(p)[tid] = v;
}

// ---------------------------------------------------------------------------
// PV (tf32 tensor): ctx[b,n,h*64+d] = sum_m attn[bh,n,m] * v[bh,m,d]
// Block: 128 rows x 64 cols (full D), BK=32, warp tile 32x32.
// ---------------------------------------------------------------------------
__global__ __launch_bounds__(256) void av_ctx_tc(
    const float* __restrict__ attn, const float* __restrict__ qkv,
    float* __restrict__ ctx)
{
    __shared__ unsigned As[32][136];   // [m][n]  (P transposed)
    __shared__ unsigned Bs[32][72];    // [m][d]  (V)

    const int bh = blockIdx.y;
    const int b  = bh >> 4;
    const int h  = bh & 15;
    const int n0 = blockIdx.x * 128;

    const float* vbase = qkv + (size_t)b * NN * 3 * CC + 2 * CC + h * DD;
    const float* arow  = attn + ((size_t)bh * NN + n0) * NN;

    const int tid = threadIdx.x;
    const int w  = tid >> 5, l = tid & 31;
    const int wr = w >> 1, wc = w & 1;
    const int g  = l >> 2, t = l & 3;

    float acc[2][4][4];
#pragma unroll
    for (int i = 0; i < 2; i++)
#pragma unroll
        for (int j = 0; j < 4; j++)
#pragma unroll
            for (int r = 0; r < 4; r++) acc[i][j][r] = 0.0f;

    for (int k0 = 0; k0 < NN; k0 += 32) {
        // P tile: 128 rows x 32 cols -> As[m][n]
#pragma unroll
        for (int j = 0; j < 4; j++) {
            const int idx = tid * 4 + j;
            const int r = idx >> 3, c4 = idx & 7;
            float4 v = *reinterpret_cast<const float4*>(
                arow + (size_t)r * NN + k0 + c4 * 4);
            As[c4 * 4 + 0][r] = f2tf(v.x);
            As[c4 * 4 + 1][r] = f2tf(v.y);
            As[c4 * 4 + 2][r] = f2tf(v.z);
            As[c4 * 4 + 3][r] = f2tf(v.w);
        }
        // V tile: 32 rows x 64 cols -> Bs[m][d]
#pragma unroll
        for (int j = 0; j < 2; j++) {
            const int idx = tid * 2 + j;
            const int r = idx >> 4, c4 = idx & 15;
            float4 v = *reinterpret_cast<const float4*>(
                vbase + (size_t)(k0 + r) * (3 * CC) + c4 * 4);
            uint4 u = {f2tf(v.x), f2tf(v.y), f2tf(v.z), f2tf(v.w)};
            *reinterpret_cast<uint4*>(&Bs[r][c4 * 4]) = u;
        }
        __syncthreads();

#pragma unroll
        for (int kk = 0; kk < 32; kk += 8) {
            unsigned a[2][4], bfr[4][2];
#pragma unroll
            for (int i = 0; i < 2; i++) {
                const int mm = wr * 32 + i * 16;
                a[i][0] = As[kk + t][mm + g];
                a[i][1] = As[kk + t][mm + g + 8];
                a[i][2] = As[kk + t + 4][mm + g];
                a[i][3] = As[kk + t + 4][mm + g + 8];
            }
#pragma unroll
            for (int j = 0; j < 4; j++) {
                const int dd = wc * 32 + j * 8;
                bfr[j][0] = Bs[kk + t][dd + g];
                bfr[j][1] = Bs[kk + t + 4][dd + g];
            }
#pragma unroll
            for (int i = 0; i < 2; i++)
#pragma unroll
                for (int j = 0; j < 4; j++)
                    mma_tf32(acc[i][j], a[i][0], a[i][1], a[i][2], a[i][3],
                             bfr[j][0], bfr[j][1]);
        }
        __syncthreads();
    }

#pragma unroll
    for (int j = 0; j < 4; j++) {
        const int col = h * DD + wc * 32 + j * 8 + t * 2;
#pragma unroll
        for (int i = 0; i < 2; i++) {
            const int r0 = n0 + wr * 32 + i * 16;
            float2 o0 = {acc[i][j][0], acc[i][j][1]};
            float2 o1 = {acc[i][j][2], acc[i][j][3]};
            *reinterpret_cast<float2*>(
                &ctx[((size_t)b * NN + r0 + g) * CC + col]) = o0;
            *reinterpret_cast<float2*>(
                &ctx[((size_t)b * NN + r0 + g + 8) * CC + col]) = o1;
        }
    }
}

// ---------------------------------------------------------------------------
extern "C" void kernel_launch(void* const* d_in, const int* in_sizes, int n_in,
                              void* d_out, int out_size)
{
    (void)in_sizes; (void)n_in; (void)out_size;
    const float* x      = (const float*)d_in[0];
    const float* w_qkv  = (const float*)d_in[1];
    const float* b_qkv  = (const float*)d_in[2];
    const float* w_proj = (const float*)d_in[3];
    const float* b_proj = (const float*)d_in[4];

    float* out  = (float*)d_out;
    float* attn = out + (size_t)BB * NN * CC;

    float* qkvp = nullptr;
    float* ctxp = nullptr;
    cudaGetSymbolAddress((void**)&qkvp, g_qkv);
    cudaGetSymbolAddress((void**)&ctxp, g_ctx);

    // 1) QKV projection (tf32 TC)
    sgemm_bias_tc<<<dim3(3 * CC / 128, BB * NN / 128), 256>>>(
        x, w_qkv, b_qkv, qkvp, BB * NN, 3 * CC, CC);

    // 2) Raw scores (tf32 TC)
    qk_scores_tc<<<dim3(NN / 128, NN / 128, BB * HH), 256>>>(qkvp, attn);

    // 3) Softmax in place
    softmax_rows<<<(unsigned)(BB * HH * NN), 256>>>(attn);

    // 4) attn @ V (tf32 TC)
    av_ctx_tc<<<dim3(NN / 128, BB * HH), 256>>>(attn, qkvp, ctxp);

    // 5) Output projection (tf32 TC)
    sgemm_bias_tc<<<dim3(CC / 128, BB * NN / 128), 256>>>(
        ctxp, w_proj, b_proj, out, BB * NN, CC, CC);
}